// round 1
// baseline (speedup 1.0000x reference)
#include <cuda_runtime.h>
#include <cuda_fp16.h>
#include <mma.h>

using namespace nvcuda;

#define S    2048
#define H    2048
#define NH   16
#define NKV  4
#define HD   128
#define FF   8192
#define NLAYER 2

// ---------------- scratch (no allocation allowed -> __device__ globals) ----------------
__device__ float  g_h[(size_t)S*H];          // residual stream fp32
__device__ int    g_amask[S];                // 1 = audio token
__device__ __half g_xn[(size_t)S*H];         // normed activations (half)
__device__ __half g_xn2[(size_t)S*H];        // second normed buffer (audio MLP branch)
__device__ float  g_qf[(size_t)S*H];         // q pre-rope
__device__ float  g_kf[(size_t)S*NKV*HD];
__device__ float  g_vf[(size_t)S*NKV*HD];
__device__ __half g_q[(size_t)NH*S*HD];      // [head][s][d]
__device__ __half g_k[(size_t)NKV*S*HD];
__device__ __half g_v[(size_t)NKV*S*HD];
__device__ float  g_scores[(size_t)NH*S*S];  // 256 MB
__device__ __half g_p[(size_t)NH*S*S];       // 128 MB
__device__ __half g_attn[(size_t)S*H];
__device__ __half g_f1[(size_t)S*FF];

// ---------------- embedding ----------------
__global__ void embed_kernel(const int* __restrict__ ids,
                             const float* __restrict__ vemb,
                             const float* __restrict__ aemb) {
    int s = blockIdx.x;
    int id = ids[s];
    bool audio = id > 31999;
    if (threadIdx.x == 0) g_amask[s] = audio ? 1 : 0;
    float* dst = g_h + (size_t)s * H;
    if (!audio) {
        const float* src = vemb + (size_t)id * H;
        for (int c = threadIdx.x; c < H; c += blockDim.x) dst[c] = src[c];
    } else {
        int tok = id - 32000;
        for (int c = threadIdx.x; c < H; c += blockDim.x) {
            float acc = 0.f;
            #pragma unroll
            for (int cb = 0; cb < 8; cb++)
                acc += aemb[((size_t)(cb * 1024 + tok)) * H + c];
            dst[c] = acc;
        }
    }
}

// ---------------- rmsnorm with per-token weight select ----------------
template<bool OUTH>
__global__ void rmsnorm_kernel(const float* __restrict__ x,
                               const float* __restrict__ wT,
                               const float* __restrict__ wA,
                               const int* __restrict__ mask,
                               __half* __restrict__ outh,
                               float* __restrict__ outf) {
    int s = blockIdx.x;
    const float* xr = x + (size_t)s * H;
    float ss = 0.f;
    for (int c = threadIdx.x; c < H; c += 256) { float v = xr[c]; ss += v * v; }
    __shared__ float red[256];
    red[threadIdx.x] = ss; __syncthreads();
    for (int o = 128; o > 0; o >>= 1) {
        if (threadIdx.x < o) red[threadIdx.x] += red[threadIdx.x + o];
        __syncthreads();
    }
    float r = rsqrtf(red[0] / (float)H + 1e-5f);
    const float* w = (mask && mask[s]) ? wA : wT;
    for (int c = threadIdx.x; c < H; c += 256) {
        float v = xr[c] * r * w[c];
        if (OUTH) outh[(size_t)s * H + c] = __float2half(v);
        else      outf[(size_t)s * H + c] = v;
    }
}

// ---------------- RoPE + layout conversion ----------------
__global__ void rope_kernel() {
    int s = blockIdx.x;
    const float LC = 0.14391156831212787f;  // ln(10000)/64
    for (int idx = threadIdx.x; idx < NH * 64; idx += blockDim.x) {
        int hh = idx >> 6, j = idx & 63;
        float inv = expf(-(float)j * LC);
        float ang = (float)s * inv;
        float sn, cs; sincosf(ang, &sn, &cs);
        float x1 = g_qf[(size_t)s * H + hh * HD + j];
        float x2 = g_qf[(size_t)s * H + hh * HD + 64 + j];
        size_t o = ((size_t)hh * S + s) * HD;
        g_q[o + j]      = __float2half(x1 * cs - x2 * sn);
        g_q[o + 64 + j] = __float2half(x2 * cs + x1 * sn);
    }
    for (int idx = threadIdx.x; idx < NKV * 64; idx += blockDim.x) {
        int hh = idx >> 6, j = idx & 63;
        float inv = expf(-(float)j * LC);
        float ang = (float)s * inv;
        float sn, cs; sincosf(ang, &sn, &cs);
        float x1 = g_kf[(size_t)s * (NKV * HD) + hh * HD + j];
        float x2 = g_kf[(size_t)s * (NKV * HD) + hh * HD + 64 + j];
        size_t o = ((size_t)hh * S + s) * HD;
        g_k[o + j]      = __float2half(x1 * cs - x2 * sn);
        g_k[o + 64 + j] = __float2half(x2 * cs + x1 * sn);
    }
    for (int idx = threadIdx.x; idx < NKV * HD; idx += blockDim.x) {
        int hh = idx >> 7, d = idx & 127;
        g_v[((size_t)hh * S + s) * HD + d] =
            __float2half(g_vf[(size_t)s * (NKV * HD) + hh * HD + d]);
    }
}

// ---------------- causal softmax ----------------
__global__ void softmax_kernel() {
    int r = blockIdx.x, h = blockIdx.y;
    const float* src = g_scores + ((size_t)h * S + r) * S;
    __half* dst = g_p + ((size_t)h * S + r) * S;
    const float scale = 0.08838834764831845f;  // 1/sqrt(128)
    int n = r + 1;
    float mx = -1e30f;
    for (int c = threadIdx.x; c < n; c += 256) mx = fmaxf(mx, src[c]);
    __shared__ float red[256];
    red[threadIdx.x] = mx; __syncthreads();
    for (int o = 128; o > 0; o >>= 1) {
        if (threadIdx.x < o) red[threadIdx.x] = fmaxf(red[threadIdx.x], red[threadIdx.x + o]);
        __syncthreads();
    }
    mx = red[0] * scale;
    __syncthreads();
    float sum = 0.f;
    for (int c = threadIdx.x; c < n; c += 256) sum += expf(src[c] * scale - mx);
    red[threadIdx.x] = sum; __syncthreads();
    for (int o = 128; o > 0; o >>= 1) {
        if (threadIdx.x < o) red[threadIdx.x] += red[threadIdx.x + o];
        __syncthreads();
    }
    float inv = 1.f / red[0];
    for (int c = threadIdx.x; c < n; c += 256)
        dst[c] = __float2half(expf(src[c] * scale - mx) * inv);
    for (int c = n + threadIdx.x; c < S; c += 256)
        dst[c] = __float2half(0.f);
}

// ---------------- generic wmma GEMM ----------------
// C[M,N] = A[M,K] (half, row-major) @ B
//   BTRANS==0: B[K,N] row-major (float -> converted to half, or half)
//   BTRANS==1: B is half [N,K] row-major, used transposed (for Q @ K^T)
// Epilogues:
enum { EPI_F32 = 0, EPI_ADDF32 = 1, EPI_H = 2, EPI_SILUH = 3, EPI_CONDADD = 4 };

#define GBM 128
#define GBN 128
#define GBK 32

template<typename BT, int BTRANS, int EPI>
__global__ void __launch_bounds__(256) gemm_kernel(
    const __half* __restrict__ A, const BT* __restrict__ B,
    float* __restrict__ Cf, __half* __restrict__ Ch,
    int M, int N, int K, int ldb, int ldc,
    size_t aBatch, size_t bBatch, int bDiv, size_t cBatch,
    const int* __restrict__ mask, int branch) {

    __shared__ __align__(16) __half As[GBM][GBK];
    __shared__ __align__(16) __half Bs[GBK][GBN];

    int tid = threadIdx.x;
    int warp = tid >> 5, lane = tid & 31;
    int wm = (warp >> 2) * 64, wn = (warp & 3) * 32;
    int bm = blockIdx.y * GBM, bn = blockIdx.x * GBN;

    A += (size_t)blockIdx.z * aBatch;
    B += (size_t)(blockIdx.z / bDiv) * bBatch;
    size_t coff = (size_t)blockIdx.z * cBatch;

    wmma::fragment<wmma::accumulator, 16, 16, 16, float> acc[4][2];
    #pragma unroll
    for (int i = 0; i < 4; i++)
        #pragma unroll
        for (int j = 0; j < 2; j++)
            wmma::fill_fragment(acc[i][j], 0.f);

    for (int k0 = 0; k0 < K; k0 += GBK) {
        // load A tile: 128x32 half
        #pragma unroll
        for (int l = 0; l < 2; l++) {
            int idx = tid + l * 256;
            int row = idx >> 2, c4 = idx & 3;
            *(int4*)(&As[row][c4 * 8]) =
                *(const int4*)(&A[(size_t)(bm + row) * K + k0 + c4 * 8]);
        }
        // load B tile: 32x128 half (converted if float)
        if constexpr (BTRANS == 1) {
            #pragma unroll
            for (int l = 0; l < 2; l++) {
                int idx = tid + l * 256;
                int n = idx >> 2, kv = idx & 3;
                int4 raw = *(const int4*)(&B[(size_t)(bn + n) * ldb + k0 + kv * 8]);
                __half h8[8];
                *(int4*)h8 = raw;
                #pragma unroll
                for (int e = 0; e < 8; e++) Bs[kv * 8 + e][n] = h8[e];
            }
        } else if constexpr (sizeof(BT) == 4) {
            #pragma unroll
            for (int l = 0; l < 4; l++) {
                int idx = tid + l * 256;
                int row = idx >> 5, c = idx & 31;
                float4 f = *(const float4*)(&B[(size_t)(k0 + row) * ldb + bn + c * 4]);
                __half2* d = (__half2*)(&Bs[row][c * 4]);
                d[0] = __floats2half2_rn(f.x, f.y);
                d[1] = __floats2half2_rn(f.z, f.w);
            }
        } else {
            #pragma unroll
            for (int l = 0; l < 2; l++) {
                int idx = tid + l * 256;
                int row = idx >> 4, c = idx & 15;
                *(int4*)(&Bs[row][c * 8]) =
                    *(const int4*)(&B[(size_t)(k0 + row) * ldb + bn + c * 8]);
            }
        }
        __syncthreads();

        #pragma unroll
        for (int kk = 0; kk < GBK; kk += 16) {
            wmma::fragment<wmma::matrix_a, 16, 16, 16, __half, wmma::row_major> af[4];
            wmma::fragment<wmma::matrix_b, 16, 16, 16, __half, wmma::row_major> bf[2];
            #pragma unroll
            for (int i = 0; i < 4; i++)
                wmma::load_matrix_sync(af[i], &As[wm + i * 16][kk], GBK);
            #pragma unroll
            for (int j = 0; j < 2; j++)
                wmma::load_matrix_sync(bf[j], &Bs[kk][wn + j * 16], GBN);
            #pragma unroll
            for (int i = 0; i < 4; i++)
                #pragma unroll
                for (int j = 0; j < 2; j++)
                    wmma::mma_sync(acc[i][j], af[i], bf[j], acc[i][j]);
        }
        __syncthreads();
    }

    // epilogue via per-warp smem bounce (reuse As: 2048 floats = 8 warps * 256)
    float* scratch = reinterpret_cast<float*>(As) + warp * 256;
    #pragma unroll
    for (int i = 0; i < 4; i++) {
        #pragma unroll
        for (int j = 0; j < 2; j++) {
            wmma::store_matrix_sync(scratch, acc[i][j], 16, wmma::mem_row_major);
            __syncwarp();
            #pragma unroll
            for (int e = 0; e < 8; e++) {
                int idx = e * 32 + lane;
                int r = idx >> 4, c = idx & 15;
                int grow = bm + wm + i * 16 + r;
                int gcol = bn + wn + j * 16 + c;
                float v = scratch[idx];
                size_t o = coff + (size_t)grow * ldc + gcol;
                if (EPI == EPI_F32)        Cf[o] = v;
                else if (EPI == EPI_ADDF32) Cf[o] += v;
                else if (EPI == EPI_H)      Ch[o] = __float2half(v);
                else if (EPI == EPI_SILUH)  Ch[o] = __float2half(v / (1.f + expf(-v)));
                else { if (mask[grow] == branch) Cf[o] += v; }
            }
            __syncwarp();
        }
    }
}

// ---------------- host launcher ----------------
extern "C" void kernel_launch(void* const* d_in, const int* in_sizes, int n_in,
                              void* d_out, int out_size) {
    const int*   ids   = (const int*)d_in[0];
    const float* vemb  = (const float*)d_in[1];
    const float* aemb  = (const float*)d_in[2];
    const float* ln_in_text   = (const float*)d_in[3];
    const float* ln_in_audio  = (const float*)d_in[4];
    const float* ln_post_text = (const float*)d_in[5];
    const float* ln_post_audio= (const float*)d_in[6];
    const float* wq    = (const float*)d_in[7];
    const float* wk    = (const float*)d_in[8];
    const float* wv    = (const float*)d_in[9];
    const float* wo    = (const float*)d_in[10];
    const float* wfct  = (const float*)d_in[11];
    const float* wprt  = (const float*)d_in[12];
    const float* wfca  = (const float*)d_in[13];
    const float* wpra  = (const float*)d_in[14];
    const float* lnf   = (const float*)d_in[15];
    float* out = (float*)d_out;

    float *h_, *qf, *kf, *vf, *scores;
    __half *xn, *xn2, *q, *k, *v, *p, *attn, *f1;
    int* am;
    cudaGetSymbolAddress((void**)&h_, g_h);
    cudaGetSymbolAddress((void**)&am, g_amask);
    cudaGetSymbolAddress((void**)&xn, g_xn);
    cudaGetSymbolAddress((void**)&xn2, g_xn2);
    cudaGetSymbolAddress((void**)&qf, g_qf);
    cudaGetSymbolAddress((void**)&kf, g_kf);
    cudaGetSymbolAddress((void**)&vf, g_vf);
    cudaGetSymbolAddress((void**)&q, g_q);
    cudaGetSymbolAddress((void**)&k, g_k);
    cudaGetSymbolAddress((void**)&v, g_v);
    cudaGetSymbolAddress((void**)&scores, g_scores);
    cudaGetSymbolAddress((void**)&p, g_p);
    cudaGetSymbolAddress((void**)&attn, g_attn);
    cudaGetSymbolAddress((void**)&f1, g_f1);

    embed_kernel<<<S, 256>>>(ids, vemb, aemb);

    for (int i = 0; i < NLAYER; i++) {
        const float* wq_i   = wq   + (size_t)i * H * H;
        const float* wk_i   = wk   + (size_t)i * H * (NKV * HD);
        const float* wv_i   = wv   + (size_t)i * H * (NKV * HD);
        const float* wo_i   = wo   + (size_t)i * H * H;
        const float* wfct_i = wfct + (size_t)i * H * FF;
        const float* wprt_i = wprt + (size_t)i * FF * H;
        const float* wfca_i = wfca + (size_t)i * H * FF;
        const float* wpra_i = wpra + (size_t)i * FF * H;

        // pre-attention norm (per-token text/audio select)
        rmsnorm_kernel<true><<<S, 256>>>(h_, ln_in_text + (size_t)i * H,
                                         ln_in_audio + (size_t)i * H, am, xn, nullptr);

        // QKV projections
        gemm_kernel<float, 0, EPI_F32><<<dim3(16, 16, 1), 256>>>(
            xn, wq_i, qf, nullptr, S, H, H, H, H, 0, 0, 1, 0, nullptr, 0);
        gemm_kernel<float, 0, EPI_F32><<<dim3(4, 16, 1), 256>>>(
            xn, wk_i, kf, nullptr, S, NKV * HD, H, NKV * HD, NKV * HD, 0, 0, 1, 0, nullptr, 0);
        gemm_kernel<float, 0, EPI_F32><<<dim3(4, 16, 1), 256>>>(
            xn, wv_i, vf, nullptr, S, NKV * HD, H, NKV * HD, NKV * HD, 0, 0, 1, 0, nullptr, 0);

        rope_kernel<<<S, 256>>>();

        // scores = Q @ K^T   (batched over 16 heads, GQA bDiv=4)
        gemm_kernel<__half, 1, EPI_F32><<<dim3(16, 16, NH), 256>>>(
            q, k, scores, nullptr, S, S, HD, HD, S,
            (size_t)S * HD, (size_t)S * HD, NH / NKV, (size_t)S * S, nullptr, 0);

        softmax_kernel<<<dim3(S, NH), 256>>>();

        // O = P @ V  -> attn [s][head*HD + d]  (half)
        gemm_kernel<__half, 0, EPI_H><<<dim3(1, 16, NH), 256>>>(
            p, v, nullptr, attn, S, HD, S, HD, H,
            (size_t)S * S, (size_t)S * HD, NH / NKV, (size_t)HD, nullptr, 0);

        // h += attn @ wo
        gemm_kernel<float, 0, EPI_ADDF32><<<dim3(16, 16, 1), 256>>>(
            attn, wo_i, h_, nullptr, S, H, H, H, H, 0, 0, 1, 0, nullptr, 0);

        // MLP: both normed versions from the SAME pre-update h
        rmsnorm_kernel<true><<<S, 256>>>(h_, ln_post_text + (size_t)i * H,
                                         ln_post_text + (size_t)i * H, nullptr, xn, nullptr);
        rmsnorm_kernel<true><<<S, 256>>>(h_, ln_post_audio + (size_t)i * H,
                                         ln_post_audio + (size_t)i * H, nullptr, xn2, nullptr);

        // text branch: f1 = silu(xn @ wfc_text); h += (f1 @ wproj_text) where !audio
        gemm_kernel<float, 0, EPI_SILUH><<<dim3(64, 16, 1), 256>>>(
            xn, wfct_i, nullptr, f1, S, FF, H, FF, FF, 0, 0, 1, 0, nullptr, 0);
        gemm_kernel<float, 0, EPI_CONDADD><<<dim3(16, 16, 1), 256>>>(
            f1, wprt_i, h_, nullptr, S, H, FF, H, H, 0, 0, 1, 0, am, 0);

        // audio branch
        gemm_kernel<float, 0, EPI_SILUH><<<dim3(64, 16, 1), 256>>>(
            xn2, wfca_i, nullptr, f1, S, FF, H, FF, FF, 0, 0, 1, 0, nullptr, 0);
        gemm_kernel<float, 0, EPI_CONDADD><<<dim3(16, 16, 1), 256>>>(
            f1, wpra_i, h_, nullptr, S, H, FF, H, H, 0, 0, 1, 0, am, 1);
    }

    // final rmsnorm -> fp32 output
    rmsnorm_kernel<false><<<S, 256>>>(h_, lnf, lnf, nullptr, nullptr, out);
}

// round 4
// speedup vs baseline: 2.6629x; 2.6629x over previous
#include <cuda_runtime.h>
#include <cuda_fp16.h>
#include <mma.h>
#include <cstdint>
#include <cstddef>

using namespace nvcuda;

#define S    2048
#define H    2048
#define NH   16
#define NKV  4
#define HD   128
#define FF   8192
#define NLAYER 2
#define QKVN 3072   // fused q(2048) + k(512) + v(512)

// ---------------- scratch (__device__ globals; no allocation allowed) ----------------
__device__ float  g_h[(size_t)S*H];            // residual stream fp32
__device__ int    g_amask[S];
__device__ __half g_xn[(size_t)S*H];
__device__ __half g_xn2[(size_t)S*H];
__device__ float  g_qkvf[(size_t)S*QKVN];      // fused qkv pre-rope fp32
__device__ __half g_q[(size_t)NH*S*HD];        // [head][s][d]
__device__ __half g_kT[(size_t)NKV*HD*S];      // [kvhead][d][s]  (transposed for QK^T)
__device__ __half g_v[(size_t)NKV*S*HD];       // [kvhead][s][d]
__device__ float  g_scores[(size_t)NH*S*S];
__device__ __half g_p[(size_t)NH*S*S];
__device__ __half g_attn[(size_t)S*H];
__device__ __half g_f1[(size_t)S*FF];

// half weights (converted once per launch)
__device__ __half g_wqkv[(size_t)NLAYER*H*QKVN];
__device__ __half g_wo2[(size_t)NLAYER*H*H];
__device__ __half g_wfct2[(size_t)NLAYER*H*FF];
__device__ __half g_wprt2[(size_t)NLAYER*FF*H];
__device__ __half g_wfca2[(size_t)NLAYER*H*FF];
__device__ __half g_wpra2[(size_t)NLAYER*FF*H];

// ---------------- weight conversion ----------------
__global__ void cvt_kernel(const float* __restrict__ src, __half* __restrict__ dst, size_t n) {
    size_t stride = (size_t)gridDim.x * blockDim.x * 8;
    for (size_t i = ((size_t)blockIdx.x * blockDim.x + threadIdx.x) * 8; i < n; i += stride) {
        float4 f0 = *(const float4*)(src + i);
        float4 f1 = *(const float4*)(src + i + 4);
        __half2 h[4] = {__floats2half2_rn(f0.x, f0.y), __floats2half2_rn(f0.z, f0.w),
                        __floats2half2_rn(f1.x, f1.y), __floats2half2_rn(f1.z, f1.w)};
        *(int4*)(dst + i) = *(int4*)h;
    }
}
// scatter rows of [rows, cols] into dst with leading dim ldd (for fused qkv layout)
__global__ void cvt_strided(const float* __restrict__ src, __half* __restrict__ dst,
                            size_t rows, int cols, int ldd) {
    size_t total = rows * (size_t)cols / 8;
    size_t stride = (size_t)gridDim.x * blockDim.x;
    for (size_t t = (size_t)blockIdx.x * blockDim.x + threadIdx.x; t < total; t += stride) {
        size_t e = t * 8;
        size_t r = e / (size_t)cols;
        int c = (int)(e - r * cols);
        float4 f0 = *(const float4*)(src + e);
        float4 f1 = *(const float4*)(src + e + 4);
        __half2 h[4] = {__floats2half2_rn(f0.x, f0.y), __floats2half2_rn(f0.z, f0.w),
                        __floats2half2_rn(f1.x, f1.y), __floats2half2_rn(f1.z, f1.w)};
        *(int4*)(dst + r * ldd + c) = *(int4*)h;
    }
}

// ---------------- embedding ----------------
__global__ void embed_kernel(const int* __restrict__ ids,
                             const float* __restrict__ vemb,
                             const float* __restrict__ aemb) {
    int s = blockIdx.x;
    int id = ids[s];
    bool audio = id > 31999;
    if (threadIdx.x == 0) g_amask[s] = audio ? 1 : 0;
    float* dst = g_h + (size_t)s * H;
    if (!audio) {
        const float* src = vemb + (size_t)id * H;
        for (int c = threadIdx.x; c < H; c += blockDim.x) dst[c] = src[c];
    } else {
        int tok = id - 32000;
        for (int c = threadIdx.x; c < H; c += blockDim.x) {
            float acc = 0.f;
            #pragma unroll
            for (int cb = 0; cb < 8; cb++)
                acc += aemb[((size_t)(cb * 1024 + tok)) * H + c];
            dst[c] = acc;
        }
    }
}

// ---------------- rmsnorm with per-token weight select ----------------
template<bool OUTH>
__global__ void rmsnorm_kernel(const float* __restrict__ x,
                               const float* __restrict__ wT,
                               const float* __restrict__ wA,
                               const int* __restrict__ mask,
                               __half* __restrict__ outh,
                               float* __restrict__ outf) {
    int s = blockIdx.x;
    const float* xr = x + (size_t)s * H;
    float ss = 0.f;
    for (int c = threadIdx.x; c < H; c += 256) { float v = xr[c]; ss += v * v; }
    __shared__ float red[256];
    red[threadIdx.x] = ss; __syncthreads();
    for (int o = 128; o > 0; o >>= 1) {
        if (threadIdx.x < o) red[threadIdx.x] += red[threadIdx.x + o];
        __syncthreads();
    }
    float r = rsqrtf(red[0] / (float)H + 1e-5f);
    const float* w = (mask && mask[s]) ? wA : wT;
    for (int c = threadIdx.x; c < H; c += 256) {
        float v = xr[c] * r * w[c];
        if (OUTH) outh[(size_t)s * H + c] = __float2half(v);
        else      outf[(size_t)s * H + c] = v;
    }
}

// ---------------- RoPE + layout conversion (reads fused qkv fp32) ----------------
__global__ void rope_kernel() {
    int s = blockIdx.x;
    const float LC = 0.14391156831212787f;  // ln(10000)/64
    const float* row = g_qkvf + (size_t)s * QKVN;
    for (int idx = threadIdx.x; idx < NH * 64; idx += blockDim.x) {
        int hh = idx >> 6, j = idx & 63;
        float inv = expf(-(float)j * LC);
        float ang = (float)s * inv;
        float sn, cs; sincosf(ang, &sn, &cs);
        float x1 = row[hh * HD + j];
        float x2 = row[hh * HD + 64 + j];
        size_t o = ((size_t)hh * S + s) * HD;
        g_q[o + j]      = __float2half(x1 * cs - x2 * sn);
        g_q[o + 64 + j] = __float2half(x2 * cs + x1 * sn);
    }
    for (int idx = threadIdx.x; idx < NKV * 64; idx += blockDim.x) {
        int hh = idx >> 6, j = idx & 63;
        float inv = expf(-(float)j * LC);
        float ang = (float)s * inv;
        float sn, cs; sincosf(ang, &sn, &cs);
        float x1 = row[2048 + hh * HD + j];
        float x2 = row[2048 + hh * HD + 64 + j];
        // transposed K: [kvhead][d][s]
        g_kT[((size_t)hh * HD + j) * S + s]      = __float2half(x1 * cs - x2 * sn);
        g_kT[((size_t)hh * HD + 64 + j) * S + s] = __float2half(x2 * cs + x1 * sn);
    }
    for (int idx = threadIdx.x; idx < NKV * HD; idx += blockDim.x) {
        int hh = idx >> 7, d = idx & 127;
        g_v[((size_t)hh * S + s) * HD + d] = __float2half(row[2560 + hh * HD + d]);
    }
}

// ---------------- single-pass causal softmax (row cached in regs) ----------------
__global__ void softmax_kernel() {
    int r = blockIdx.x, h = blockIdx.y;
    const float* src = g_scores + ((size_t)h * S + r) * S;
    __half* dst = g_p + ((size_t)h * S + r) * S;
    const float scale = 0.08838834764831845f;  // 1/sqrt(128)
    int n = r + 1;
    float vals[8];
    float mx = -1e30f;
    #pragma unroll
    for (int i = 0; i < 8; i++) {
        int c = threadIdx.x + i * 256;
        vals[i] = (c < n) ? src[c] * scale : -1e30f;
        mx = fmaxf(mx, vals[i]);
    }
    __shared__ float red[256];
    red[threadIdx.x] = mx; __syncthreads();
    for (int o = 128; o > 0; o >>= 1) {
        if (threadIdx.x < o) red[threadIdx.x] = fmaxf(red[threadIdx.x], red[threadIdx.x + o]);
        __syncthreads();
    }
    mx = red[0]; __syncthreads();
    float sum = 0.f;
    #pragma unroll
    for (int i = 0; i < 8; i++) { vals[i] = expf(vals[i] - mx); sum += vals[i]; }
    red[threadIdx.x] = sum; __syncthreads();
    for (int o = 128; o > 0; o >>= 1) {
        if (threadIdx.x < o) red[threadIdx.x] += red[threadIdx.x + o];
        __syncthreads();
    }
    float inv = 1.f / red[0];
    #pragma unroll
    for (int i = 0; i < 8; i++) {
        int c = threadIdx.x + i * 256;
        dst[c] = __float2half(vals[i] * inv);
    }
}

// ---------------- cp.async helpers ----------------
__device__ __forceinline__ void cp16(void* smem, const void* gmem) {
    unsigned int s = (unsigned int)__cvta_generic_to_shared(smem);
    asm volatile("cp.async.cg.shared.global [%0], [%1], 16;\n" :: "r"(s), "l"(gmem));
}
__device__ __forceinline__ void cp_commit() { asm volatile("cp.async.commit_group;\n"); }
template<int N> __device__ __forceinline__ void cp_wait() {
    asm volatile("cp.async.wait_group %0;\n" :: "n"(N));
}

// ---------------- double-buffered half GEMM (cp.async + wmma) ----------------
// C[M,N] = A[M,K] @ B[K,N], both half row-major, fp32 accumulate.
enum { EPI_F32 = 0, EPI_ADDF32 = 1, EPI_H = 2, EPI_SILUH = 3, EPI_CONDADD = 4 };

#define BM 128
#define BN 128
#define BK 32
#define LDA 40
#define LDB 136

template<int EPI, bool CAUSAL>
__global__ void __launch_bounds__(256, 2) hgemm(
    const __half* __restrict__ A, const __half* __restrict__ B,
    float* __restrict__ Cf, __half* __restrict__ Ch,
    int M, int N, int K, int ldb, int ldc,
    size_t aBatch, size_t bBatch, int bDiv, size_t cBatch,
    const int* __restrict__ mask, int branch) {

    int bm = blockIdx.y * BM, bn = blockIdx.x * BN;
    if (CAUSAL && bn > bm + (BM - 1)) return;   // fully-masked score block

    __shared__ __align__(16) __half As[2][BM][LDA];
    __shared__ __align__(16) __half Bs[2][BK][LDB];

    int tid = threadIdx.x;
    int warp = tid >> 5, lane = tid & 31;
    int wm = (warp >> 2) * 64, wn = (warp & 3) * 32;

    A += (size_t)blockIdx.z * aBatch;
    B += (size_t)(blockIdx.z / bDiv) * bBatch;
    size_t coff = (size_t)blockIdx.z * cBatch;

    wmma::fragment<wmma::accumulator, 16, 16, 16, float> acc[4][2];
    #pragma unroll
    for (int i = 0; i < 4; i++)
        #pragma unroll
        for (int j = 0; j < 2; j++)
            wmma::fill_fragment(acc[i][j], 0.f);

    auto load_tile = [&](int kt, int buf) {
        int k0 = kt * BK;
        // A tile: 128 rows x 32 cols = 512 chunks of 8 halves
        #pragma unroll
        for (int l = 0; l < 2; l++) {
            int idx = tid + l * 256;
            int r = idx >> 2, c = (idx & 3) * 8;
            cp16(&As[buf][r][c], &A[(size_t)(bm + r) * K + k0 + c]);
        }
        // B tile: 32 rows x 128 cols = 512 chunks of 8 halves
        #pragma unroll
        for (int l = 0; l < 2; l++) {
            int idx = tid + l * 256;
            int r = idx >> 4, c = (idx & 15) * 8;
            cp16(&Bs[buf][r][c], &B[(size_t)(k0 + r) * ldb + bn + c]);
        }
    };

    int KT = K / BK;
    load_tile(0, 0);
    cp_commit();

    for (int kt = 0; kt < KT; kt++) {
        cp_wait<0>();
        __syncthreads();
        if (kt + 1 < KT) load_tile(kt + 1, (kt + 1) & 1);
        cp_commit();

        int buf = kt & 1;
        #pragma unroll
        for (int kk = 0; kk < BK; kk += 16) {
            wmma::fragment<wmma::matrix_a, 16, 16, 16, __half, wmma::row_major> af[4];
            wmma::fragment<wmma::matrix_b, 16, 16, 16, __half, wmma::row_major> bf[2];
            #pragma unroll
            for (int i = 0; i < 4; i++)
                wmma::load_matrix_sync(af[i], &As[buf][wm + i * 16][kk], LDA);
            #pragma unroll
            for (int j = 0; j < 2; j++)
                wmma::load_matrix_sync(bf[j], &Bs[buf][kk][wn + j * 16], LDB);
            #pragma unroll
            for (int i = 0; i < 4; i++)
                #pragma unroll
                for (int j = 0; j < 2; j++)
                    wmma::mma_sync(acc[i][j], af[i], bf[j], acc[i][j]);
        }
    }
    __syncthreads();

    // epilogue via per-warp smem bounce (8 warps * 256 floats = 8KB, fits in As)
    float* scratch = reinterpret_cast<float*>(As) + warp * 256;
    #pragma unroll
    for (int i = 0; i < 4; i++) {
        #pragma unroll
        for (int j = 0; j < 2; j++) {
            wmma::store_matrix_sync(scratch, acc[i][j], 16, wmma::mem_row_major);
            __syncwarp();
            #pragma unroll
            for (int e = 0; e < 8; e++) {
                int idx = e * 32 + lane;
                int r = idx >> 4, c = idx & 15;
                int grow = bm + wm + i * 16 + r;
                int gcol = bn + wn + j * 16 + c;
                float v = scratch[idx];
                size_t o = coff + (size_t)grow * ldc + gcol;
                if (EPI == EPI_F32)         Cf[o] = v;
                else if (EPI == EPI_ADDF32) Cf[o] += v;
                else if (EPI == EPI_H)      Ch[o] = __float2half(v);
                else if (EPI == EPI_SILUH)  Ch[o] = __float2half(v / (1.f + expf(-v)));
                else { if (mask[grow] == branch) Cf[o] += v; }
            }
            __syncwarp();
        }
    }
}

// ---------------- host launcher ----------------
extern "C" void kernel_launch(void* const* d_in, const int* in_sizes, int n_in,
                              void* d_out, int out_size) {
    const int*   ids   = (const int*)d_in[0];
    const float* vemb  = (const float*)d_in[1];
    const float* aemb  = (const float*)d_in[2];
    const float* ln_in_text   = (const float*)d_in[3];
    const float* ln_in_audio  = (const float*)d_in[4];
    const float* ln_post_text = (const float*)d_in[5];
    const float* ln_post_audio= (const float*)d_in[6];
    const float* wq    = (const float*)d_in[7];
    const float* wk    = (const float*)d_in[8];
    const float* wv    = (const float*)d_in[9];
    const float* wo    = (const float*)d_in[10];
    const float* wfct  = (const float*)d_in[11];
    const float* wprt  = (const float*)d_in[12];
    const float* wfca  = (const float*)d_in[13];
    const float* wpra  = (const float*)d_in[14];
    const float* lnf   = (const float*)d_in[15];
    float* out = (float*)d_out;

    float *h_, *qkvf, *scores;
    __half *xn, *xn2, *q, *kT, *v, *p, *attn, *f1;
    __half *wqkv2, *wo2, *wfct2, *wprt2, *wfca2, *wpra2;
    int* am;
    cudaGetSymbolAddress((void**)&h_, g_h);
    cudaGetSymbolAddress((void**)&am, g_amask);
    cudaGetSymbolAddress((void**)&xn, g_xn);
    cudaGetSymbolAddress((void**)&xn2, g_xn2);
    cudaGetSymbolAddress((void**)&qkvf, g_qkvf);
    cudaGetSymbolAddress((void**)&q, g_q);
    cudaGetSymbolAddress((void**)&kT, g_kT);
    cudaGetSymbolAddress((void**)&v, g_v);
    cudaGetSymbolAddress((void**)&scores, g_scores);
    cudaGetSymbolAddress((void**)&p, g_p);
    cudaGetSymbolAddress((void**)&attn, g_attn);
    cudaGetSymbolAddress((void**)&f1, g_f1);
    cudaGetSymbolAddress((void**)&wqkv2, g_wqkv);
    cudaGetSymbolAddress((void**)&wo2, g_wo2);
    cudaGetSymbolAddress((void**)&wfct2, g_wfct2);
    cudaGetSymbolAddress((void**)&wprt2, g_wprt2);
    cudaGetSymbolAddress((void**)&wfca2, g_wfca2);
    cudaGetSymbolAddress((void**)&wpra2, g_wpra2);

    // ---- weight conversion (once per launch) ----
    cvt_strided<<<1024, 256>>>(wq, wqkv2,        (size_t)NLAYER * H, H,        QKVN);
    cvt_strided<<<1024, 256>>>(wk, wqkv2 + 2048, (size_t)NLAYER * H, NKV * HD, QKVN);
    cvt_strided<<<1024, 256>>>(wv, wqkv2 + 2560, (size_t)NLAYER * H, NKV * HD, QKVN);
    cvt_kernel<<<1024, 256>>>(wo,   wo2,   (size_t)NLAYER * H * H);
    cvt_kernel<<<1024, 256>>>(wfct, wfct2, (size_t)NLAYER * H * FF);
    cvt_kernel<<<1024, 256>>>(wprt, wprt2, (size_t)NLAYER * FF * H);
    cvt_kernel<<<1024, 256>>>(wfca, wfca2, (size_t)NLAYER * H * FF);
    cvt_kernel<<<1024, 256>>>(wpra, wpra2, (size_t)NLAYER * FF * H);

    embed_kernel<<<S, 256>>>(ids, vemb, aemb);

    for (int i = 0; i < NLAYER; i++) {
        __half* wqkv_i = wqkv2 + (size_t)i * H * QKVN;
        __half* wo_i   = wo2   + (size_t)i * H * H;
        __half* wfct_i = wfct2 + (size_t)i * H * FF;
        __half* wprt_i = wprt2 + (size_t)i * FF * H;
        __half* wfca_i = wfca2 + (size_t)i * H * FF;
        __half* wpra_i = wpra2 + (size_t)i * FF * H;

        // pre-attention norm (per-token text/audio select)
        rmsnorm_kernel<true><<<S, 256>>>(h_, ln_in_text + (size_t)i * H,
                                         ln_in_audio + (size_t)i * H, am, xn, nullptr);

        // fused QKV projection: [S,H] @ [H,3072]
        hgemm<EPI_F32, false><<<dim3(QKVN / BN, S / BM, 1), 256>>>(
            xn, wqkv_i, qkvf, nullptr, S, QKVN, H, QKVN, QKVN, 0, 0, 1, 0, nullptr, 0);

        rope_kernel<<<S, 256>>>();

        // scores = Q @ K^T  (kT is [kv][d][s] so B is plain row-major; causal block skip)
        hgemm<EPI_F32, true><<<dim3(S / BN, S / BM, NH), 256>>>(
            q, kT, scores, nullptr, S, S, HD, S, S,
            (size_t)S * HD, (size_t)HD * S, NH / NKV, (size_t)S * S, nullptr, 0);

        softmax_kernel<<<dim3(S, NH), 256>>>();

        // O = P @ V -> attn [s][head*HD+d]
        hgemm<EPI_H, false><<<dim3(HD / BN, S / BM, NH), 256>>>(
            p, v, nullptr, attn, S, HD, S, HD, H,
            (size_t)S * S, (size_t)S * HD, NH / NKV, (size_t)HD, nullptr, 0);

        // h += attn @ wo
        hgemm<EPI_ADDF32, false><<<dim3(H / BN, S / BM, 1), 256>>>(
            attn, wo_i, h_, nullptr, S, H, H, H, H, 0, 0, 1, 0, nullptr, 0);

        // MLP norms (both from same pre-update h)
        rmsnorm_kernel<true><<<S, 256>>>(h_, ln_post_text + (size_t)i * H,
                                         ln_post_text + (size_t)i * H, nullptr, xn, nullptr);
        rmsnorm_kernel<true><<<S, 256>>>(h_, ln_post_audio + (size_t)i * H,
                                         ln_post_audio + (size_t)i * H, nullptr, xn2, nullptr);

        // text branch
        hgemm<EPI_SILUH, false><<<dim3(FF / BN, S / BM, 1), 256>>>(
            xn, wfct_i, nullptr, f1, S, FF, H, FF, FF, 0, 0, 1, 0, nullptr, 0);
        hgemm<EPI_CONDADD, false><<<dim3(H / BN, S / BM, 1), 256>>>(
            f1, wprt_i, h_, nullptr, S, H, FF, H, H, 0, 0, 1, 0, am, 0);

        // audio branch
        hgemm<EPI_SILUH, false><<<dim3(FF / BN, S / BM, 1), 256>>>(
            xn2, wfca_i, nullptr, f1, S, FF, H, FF, FF, 0, 0, 1, 0, nullptr, 0);
        hgemm<EPI_CONDADD, false><<<dim3(H / BN, S / BM, 1), 256>>>(
            f1, wpra_i, h_, nullptr, S, H, FF, H, H, 0, 0, 1, 0, am, 1);
    }

    rmsnorm_kernel<false><<<S, 256>>>(h_, lnf, lnf, nullptr, nullptr, out);
}

// round 6
// speedup vs baseline: 2.9122x; 1.0936x over previous
#include <cuda_runtime.h>
#include <cuda_fp16.h>
#include <mma.h>
#include <cstdint>
#include <cstddef>

using namespace nvcuda;

#define S    2048
#define H    2048
#define NH   16
#define NKV  4
#define HD   128
#define FF   8192
#define NLAYER 2
#define QKVN 3072   // fused q(2048) + k(512) + v(512)

// ---------------- scratch (__device__ globals; no allocation allowed) ----------------
__device__ float  g_h[(size_t)S*H];            // residual stream fp32
__device__ int    g_amask[S];
__device__ int    g_idx[S];                    // compact order: text tokens then audio tokens
__device__ int    g_cnt[1];                    // number of text tokens
__device__ __half g_xn[(size_t)S*H];           // pre-attn normed
__device__ __half g_xc[(size_t)S*H];           // gathered post-norm (compact order)
__device__ float  g_qkvf[(size_t)S*QKVN];      // fused qkv pre-rope fp32
__device__ __half g_q[(size_t)NH*S*HD];        // [head][s][d]
__device__ __half g_kT[(size_t)NKV*HD*S];      // [kvhead][d][s]
__device__ __half g_v[(size_t)NKV*S*HD];       // [kvhead][s][d]
__device__ float  g_scores[(size_t)NH*S*S];
__device__ __half g_p[(size_t)NH*S*S];
__device__ __half g_attn[(size_t)S*H];
__device__ __half g_f1[(size_t)S*FF];          // compact-order MLP hidden

// half weights (converted once per launch)
__device__ __half g_wqkv[(size_t)NLAYER*H*QKVN];
__device__ __half g_wo2[(size_t)NLAYER*H*H];
__device__ __half g_wfct2[(size_t)NLAYER*H*FF];
__device__ __half g_wprt2[(size_t)NLAYER*FF*H];
__device__ __half g_wfca2[(size_t)NLAYER*H*FF];
__device__ __half g_wpra2[(size_t)NLAYER*FF*H];

// ---------------- weight conversion ----------------
__global__ void cvt_kernel(const float* __restrict__ src, __half* __restrict__ dst, size_t n) {
    size_t stride = (size_t)gridDim.x * blockDim.x * 8;
    for (size_t i = ((size_t)blockIdx.x * blockDim.x + threadIdx.x) * 8; i < n; i += stride) {
        float4 f0 = *(const float4*)(src + i);
        float4 f1 = *(const float4*)(src + i + 4);
        __half2 h[4] = {__floats2half2_rn(f0.x, f0.y), __floats2half2_rn(f0.z, f0.w),
                        __floats2half2_rn(f1.x, f1.y), __floats2half2_rn(f1.z, f1.w)};
        *(int4*)(dst + i) = *(int4*)h;
    }
}
__global__ void cvt_strided(const float* __restrict__ src, __half* __restrict__ dst,
                            size_t rows, int cols, int ldd) {
    size_t total = rows * (size_t)cols / 8;
    size_t stride = (size_t)gridDim.x * blockDim.x;
    for (size_t t = (size_t)blockIdx.x * blockDim.x + threadIdx.x; t < total; t += stride) {
        size_t e = t * 8;
        size_t r = e / (size_t)cols;
        int c = (int)(e - r * cols);
        float4 f0 = *(const float4*)(src + e);
        float4 f1 = *(const float4*)(src + e + 4);
        __half2 h[4] = {__floats2half2_rn(f0.x, f0.y), __floats2half2_rn(f0.z, f0.w),
                        __floats2half2_rn(f1.x, f1.y), __floats2half2_rn(f1.z, f1.w)};
        *(int4*)(dst + r * ldd + c) = *(int4*)h;
    }
}

// ---------------- embedding ----------------
__global__ void embed_kernel(const int* __restrict__ ids,
                             const float* __restrict__ vemb,
                             const float* __restrict__ aemb) {
    int s = blockIdx.x;
    int id = ids[s];
    bool audio = id > 31999;
    if (threadIdx.x == 0) g_amask[s] = audio ? 1 : 0;
    float* dst = g_h + (size_t)s * H;
    if (!audio) {
        const float* src = vemb + (size_t)id * H;
        for (int c = threadIdx.x; c < H; c += blockDim.x) dst[c] = src[c];
    } else {
        int tok = id - 32000;
        for (int c = threadIdx.x; c < H; c += blockDim.x) {
            float acc = 0.f;
            #pragma unroll
            for (int cb = 0; cb < 8; cb++)
                acc += aemb[((size_t)(cb * 1024 + tok)) * H + c];
            dst[c] = acc;
        }
    }
}

// ---------------- partition: compact text indices then audio indices ----------------
__global__ void partition_kernel() {
    __shared__ int tcnt[256], acnt[256];
    __shared__ int toff[256], aoff[256];
    int t = threadIdx.x;           // 256 threads, 8 tokens each
    int base = t * 8;
    int ct = 0, ca = 0;
    #pragma unroll
    for (int i = 0; i < 8; i++) { if (g_amask[base + i]) ca++; else ct++; }
    tcnt[t] = ct; acnt[t] = ca;
    __syncthreads();
    if (t == 0) {
        int st = 0, sa = 0;
        for (int i = 0; i < 256; i++) {
            toff[i] = st; st += tcnt[i];
            aoff[i] = sa; sa += acnt[i];
        }
        g_cnt[0] = st;
    }
    __syncthreads();
    int cntT = g_cnt[0];
    int pt = toff[t], pa = cntT + aoff[t];
    #pragma unroll
    for (int i = 0; i < 8; i++) {
        int s = base + i;
        if (g_amask[s]) g_idx[pa++] = s;
        else            g_idx[pt++] = s;
    }
}

// ---------------- rmsnorm with per-token weight select (natural order) ----------------
template<bool OUTH>
__global__ void rmsnorm_kernel(const float* __restrict__ x,
                               const float* __restrict__ wT,
                               const float* __restrict__ wA,
                               const int* __restrict__ mask,
                               __half* __restrict__ outh,
                               float* __restrict__ outf) {
    int s = blockIdx.x;
    const float* xr = x + (size_t)s * H;
    float ss = 0.f;
    for (int c = threadIdx.x; c < H; c += 256) { float v = xr[c]; ss += v * v; }
    __shared__ float red[256];
    red[threadIdx.x] = ss; __syncthreads();
    for (int o = 128; o > 0; o >>= 1) {
        if (threadIdx.x < o) red[threadIdx.x] += red[threadIdx.x + o];
        __syncthreads();
    }
    float r = rsqrtf(red[0] / (float)H + 1e-5f);
    const float* w = (mask && mask[s]) ? wA : wT;
    for (int c = threadIdx.x; c < H; c += 256) {
        float v = xr[c] * r * w[c];
        if (OUTH) outh[(size_t)s * H + c] = __float2half(v);
        else      outf[(size_t)s * H + c] = v;
    }
}

// ---------------- rmsnorm + gather into compact order ----------------
__global__ void rmsnorm_gather(const float* __restrict__ x,
                               const float* __restrict__ wT,
                               const float* __restrict__ wA,
                               __half* __restrict__ out) {
    int p = blockIdx.x;                 // compact position
    int cnt = g_cnt[0];
    int s = g_idx[p];
    const float* xr = x + (size_t)s * H;
    float ss = 0.f;
    for (int c = threadIdx.x; c < H; c += 256) { float v = xr[c]; ss += v * v; }
    __shared__ float red[256];
    red[threadIdx.x] = ss; __syncthreads();
    for (int o = 128; o > 0; o >>= 1) {
        if (threadIdx.x < o) red[threadIdx.x] += red[threadIdx.x + o];
        __syncthreads();
    }
    float r = rsqrtf(red[0] / (float)H + 1e-5f);
    const float* w = (p < cnt) ? wT : wA;
    for (int c = threadIdx.x; c < H; c += 256)
        out[(size_t)p * H + c] = __float2half(xr[c] * r * w[c]);
}

// ---------------- RoPE + layout conversion ----------------
__global__ void rope_kernel() {
    int s = blockIdx.x;
    const float LC = 0.14391156831212787f;  // ln(10000)/64
    const float* row = g_qkvf + (size_t)s * QKVN;
    for (int idx = threadIdx.x; idx < NH * 64; idx += blockDim.x) {
        int hh = idx >> 6, j = idx & 63;
        float inv = expf(-(float)j * LC);
        float ang = (float)s * inv;
        float sn, cs; sincosf(ang, &sn, &cs);
        float x1 = row[hh * HD + j];
        float x2 = row[hh * HD + 64 + j];
        size_t o = ((size_t)hh * S + s) * HD;
        g_q[o + j]      = __float2half(x1 * cs - x2 * sn);
        g_q[o + 64 + j] = __float2half(x2 * cs + x1 * sn);
    }
    for (int idx = threadIdx.x; idx < NKV * 64; idx += blockDim.x) {
        int hh = idx >> 6, j = idx & 63;
        float inv = expf(-(float)j * LC);
        float ang = (float)s * inv;
        float sn, cs; sincosf(ang, &sn, &cs);
        float x1 = row[2048 + hh * HD + j];
        float x2 = row[2048 + hh * HD + 64 + j];
        g_kT[((size_t)hh * HD + j) * S + s]      = __float2half(x1 * cs - x2 * sn);
        g_kT[((size_t)hh * HD + 64 + j) * S + s] = __float2half(x2 * cs + x1 * sn);
    }
    for (int idx = threadIdx.x; idx < NKV * HD; idx += blockDim.x) {
        int hh = idx >> 7, d = idx & 127;
        g_v[((size_t)hh * S + s) * HD + d] = __float2half(row[2560 + hh * HD + d]);
    }
}

// ---------------- single-pass causal softmax ----------------
__global__ void softmax_kernel() {
    int r = blockIdx.x, h = blockIdx.y;
    const float* src = g_scores + ((size_t)h * S + r) * S;
    __half* dst = g_p + ((size_t)h * S + r) * S;
    const float scale = 0.08838834764831845f;  // 1/sqrt(128)
    int n = r + 1;
    float vals[8];
    float mx = -1e30f;
    #pragma unroll
    for (int i = 0; i < 8; i++) {
        int c = threadIdx.x + i * 256;
        vals[i] = (c < n) ? src[c] * scale : -1e30f;
        mx = fmaxf(mx, vals[i]);
    }
    __shared__ float red[256];
    red[threadIdx.x] = mx; __syncthreads();
    for (int o = 128; o > 0; o >>= 1) {
        if (threadIdx.x < o) red[threadIdx.x] = fmaxf(red[threadIdx.x], red[threadIdx.x + o]);
        __syncthreads();
    }
    mx = red[0]; __syncthreads();
    float sum = 0.f;
    #pragma unroll
    for (int i = 0; i < 8; i++) { vals[i] = expf(vals[i] - mx); sum += vals[i]; }
    red[threadIdx.x] = sum; __syncthreads();
    for (int o = 128; o > 0; o >>= 1) {
        if (threadIdx.x < o) red[threadIdx.x] += red[threadIdx.x + o];
        __syncthreads();
    }
    float inv = 1.f / red[0];
    #pragma unroll
    for (int i = 0; i < 8; i++) {
        int c = threadIdx.x + i * 256;
        dst[c] = __float2half(vals[i] * inv);
    }
}

// ---------------- cp.async helpers ----------------
__device__ __forceinline__ void cp16(void* smem, const void* gmem) {
    unsigned int s = (unsigned int)__cvta_generic_to_shared(smem);
    asm volatile("cp.async.cg.shared.global [%0], [%1], 16;\n" :: "r"(s), "l"(gmem));
}
__device__ __forceinline__ void cp_commit() { asm volatile("cp.async.commit_group;\n"); }
template<int N> __device__ __forceinline__ void cp_wait() {
    asm volatile("cp.async.wait_group %0;\n" :: "n"(N));
}

// ---------------- double-buffered half GEMM (cp.async + wmma) ----------------
// C[M,N] = A[M,K] @ B[K,N], both half row-major, fp32 accumulate.
// rangeMode: 0 = all rows; 1 = rows [0, cnt); 2 = rows [cnt, M)
enum { EPI_F32 = 0, EPI_ADDF32 = 1, EPI_H = 2, EPI_SILUH = 3, EPI_SCATTER = 4 };

#define BM 128
#define BN 128
#define BK 32
#define LDA 40
#define LDB 136

template<int EPI, bool CAUSAL>
__global__ void __launch_bounds__(256, 2) hgemm(
    const __half* __restrict__ A, const __half* __restrict__ B,
    float* __restrict__ Cf, __half* __restrict__ Ch,
    int M, int N, int K, int ldb, int ldc,
    size_t aBatch, size_t bBatch, int bDiv, size_t cBatch,
    const int* __restrict__ cntPtr, int rangeMode, const int* __restrict__ idx) {

    int bm = blockIdx.y * BM, bn = blockIdx.x * BN;
    if (CAUSAL && bn > bm + (BM - 1)) return;   // fully-masked score block

    int lo = 0, hi = M;
    if (rangeMode == 1) hi = cntPtr[0];
    else if (rangeMode == 2) lo = cntPtr[0];
    if (bm >= hi || bm + BM <= lo) return;

    __shared__ __align__(16) __half As[2][BM][LDA];
    __shared__ __align__(16) __half Bs[2][BK][LDB];

    int tid = threadIdx.x;
    int warp = tid >> 5, lane = tid & 31;
    int wm = (warp >> 2) * 64, wn = (warp & 3) * 32;

    A += (size_t)blockIdx.z * aBatch;
    B += (size_t)(blockIdx.z / bDiv) * bBatch;
    size_t coff = (size_t)blockIdx.z * cBatch;

    wmma::fragment<wmma::accumulator, 16, 16, 16, float> acc[4][2];
    #pragma unroll
    for (int i = 0; i < 4; i++)
        #pragma unroll
        for (int j = 0; j < 2; j++)
            wmma::fill_fragment(acc[i][j], 0.f);

    auto load_tile = [&](int kt, int buf) {
        int k0 = kt * BK;
        #pragma unroll
        for (int l = 0; l < 2; l++) {
            int idx2 = tid + l * 256;
            int r = idx2 >> 2, c = (idx2 & 3) * 8;
            cp16(&As[buf][r][c], &A[(size_t)(bm + r) * K + k0 + c]);
        }
        #pragma unroll
        for (int l = 0; l < 2; l++) {
            int idx2 = tid + l * 256;
            int r = idx2 >> 4, c = (idx2 & 15) * 8;
            cp16(&Bs[buf][r][c], &B[(size_t)(k0 + r) * ldb + bn + c]);
        }
    };

    int KT = K / BK;
    load_tile(0, 0);
    cp_commit();

    for (int kt = 0; kt < KT; kt++) {
        cp_wait<0>();
        __syncthreads();
        if (kt + 1 < KT) load_tile(kt + 1, (kt + 1) & 1);
        cp_commit();

        int buf = kt & 1;
        #pragma unroll
        for (int kk = 0; kk < BK; kk += 16) {
            wmma::fragment<wmma::matrix_a, 16, 16, 16, __half, wmma::row_major> af[4];
            wmma::fragment<wmma::matrix_b, 16, 16, 16, __half, wmma::row_major> bf[2];
            #pragma unroll
            for (int i = 0; i < 4; i++)
                wmma::load_matrix_sync(af[i], &As[buf][wm + i * 16][kk], LDA);
            #pragma unroll
            for (int j = 0; j < 2; j++)
                wmma::load_matrix_sync(bf[j], &Bs[buf][kk][wn + j * 16], LDB);
            #pragma unroll
            for (int i = 0; i < 4; i++)
                #pragma unroll
                for (int j = 0; j < 2; j++)
                    wmma::mma_sync(acc[i][j], af[i], bf[j], acc[i][j]);
        }
    }
    __syncthreads();

    // epilogue via per-warp smem bounce
    float* scratch = reinterpret_cast<float*>(As) + warp * 256;
    #pragma unroll
    for (int i = 0; i < 4; i++) {
        #pragma unroll
        for (int j = 0; j < 2; j++) {
            wmma::store_matrix_sync(scratch, acc[i][j], 16, wmma::mem_row_major);
            __syncwarp();
            #pragma unroll
            for (int e = 0; e < 8; e++) {
                int idx2 = e * 32 + lane;
                int r = idx2 >> 4, c = idx2 & 15;
                int grow = bm + wm + i * 16 + r;
                int gcol = bn + wn + j * 16 + c;
                if (grow >= lo && grow < hi) {
                    float v = scratch[idx2];
                    if (EPI == EPI_F32)         Cf[coff + (size_t)grow * ldc + gcol] = v;
                    else if (EPI == EPI_ADDF32) Cf[coff + (size_t)grow * ldc + gcol] += v;
                    else if (EPI == EPI_H)      Ch[coff + (size_t)grow * ldc + gcol] = __float2half(v);
                    else if (EPI == EPI_SILUH)  Ch[coff + (size_t)grow * ldc + gcol] = __float2half(v / (1.f + expf(-v)));
                    else { int s2 = idx[grow]; Cf[(size_t)s2 * ldc + gcol] += v; }
                }
            }
            __syncwarp();
        }
    }
}

// ---------------- host launcher ----------------
extern "C" void kernel_launch(void* const* d_in, const int* in_sizes, int n_in,
                              void* d_out, int out_size) {
    const int*   ids   = (const int*)d_in[0];
    const float* vemb  = (const float*)d_in[1];
    const float* aemb  = (const float*)d_in[2];
    const float* ln_in_text   = (const float*)d_in[3];
    const float* ln_in_audio  = (const float*)d_in[4];
    const float* ln_post_text = (const float*)d_in[5];
    const float* ln_post_audio= (const float*)d_in[6];
    const float* wq    = (const float*)d_in[7];
    const float* wk    = (const float*)d_in[8];
    const float* wv    = (const float*)d_in[9];
    const float* wo    = (const float*)d_in[10];
    const float* wfct  = (const float*)d_in[11];
    const float* wprt  = (const float*)d_in[12];
    const float* wfca  = (const float*)d_in[13];
    const float* wpra  = (const float*)d_in[14];
    const float* lnf   = (const float*)d_in[15];
    float* out = (float*)d_out;

    float *h_, *qkvf, *scores;
    __half *xn, *xc, *q, *kT, *v, *p, *attn, *f1;
    __half *wqkv2, *wo2, *wfct2, *wprt2, *wfca2, *wpra2;
    int *am, *idx, *cnt;
    cudaGetSymbolAddress((void**)&h_, g_h);
    cudaGetSymbolAddress((void**)&am, g_amask);
    cudaGetSymbolAddress((void**)&idx, g_idx);
    cudaGetSymbolAddress((void**)&cnt, g_cnt);
    cudaGetSymbolAddress((void**)&xn, g_xn);
    cudaGetSymbolAddress((void**)&xc, g_xc);
    cudaGetSymbolAddress((void**)&qkvf, g_qkvf);
    cudaGetSymbolAddress((void**)&q, g_q);
    cudaGetSymbolAddress((void**)&kT, g_kT);
    cudaGetSymbolAddress((void**)&v, g_v);
    cudaGetSymbolAddress((void**)&scores, g_scores);
    cudaGetSymbolAddress((void**)&p, g_p);
    cudaGetSymbolAddress((void**)&attn, g_attn);
    cudaGetSymbolAddress((void**)&f1, g_f1);
    cudaGetSymbolAddress((void**)&wqkv2, g_wqkv);
    cudaGetSymbolAddress((void**)&wo2, g_wo2);
    cudaGetSymbolAddress((void**)&wfct2, g_wfct2);
    cudaGetSymbolAddress((void**)&wprt2, g_wprt2);
    cudaGetSymbolAddress((void**)&wfca2, g_wfca2);
    cudaGetSymbolAddress((void**)&wpra2, g_wpra2);

    // ---- weight conversion (once per launch) ----
    cvt_strided<<<1024, 256>>>(wq, wqkv2,        (size_t)NLAYER * H, H,        QKVN);
    cvt_strided<<<1024, 256>>>(wk, wqkv2 + 2048, (size_t)NLAYER * H, NKV * HD, QKVN);
    cvt_strided<<<1024, 256>>>(wv, wqkv2 + 2560, (size_t)NLAYER * H, NKV * HD, QKVN);
    cvt_kernel<<<1024, 256>>>(wo,   wo2,   (size_t)NLAYER * H * H);
    cvt_kernel<<<1024, 256>>>(wfct, wfct2, (size_t)NLAYER * H * FF);
    cvt_kernel<<<1024, 256>>>(wprt, wprt2, (size_t)NLAYER * FF * H);
    cvt_kernel<<<1024, 256>>>(wfca, wfca2, (size_t)NLAYER * H * FF);
    cvt_kernel<<<1024, 256>>>(wpra, wpra2, (size_t)NLAYER * FF * H);

    embed_kernel<<<S, 256>>>(ids, vemb, aemb);
    partition_kernel<<<1, 256>>>();

    for (int i = 0; i < NLAYER; i++) {
        __half* wqkv_i = wqkv2 + (size_t)i * H * QKVN;
        __half* wo_i   = wo2   + (size_t)i * H * H;
        __half* wfct_i = wfct2 + (size_t)i * H * FF;
        __half* wprt_i = wprt2 + (size_t)i * FF * H;
        __half* wfca_i = wfca2 + (size_t)i * H * FF;
        __half* wpra_i = wpra2 + (size_t)i * FF * H;

        // pre-attention norm (per-token text/audio select, natural order)
        rmsnorm_kernel<true><<<S, 256>>>(h_, ln_in_text + (size_t)i * H,
                                         ln_in_audio + (size_t)i * H, am, xn, nullptr);

        // fused QKV projection: [S,H] @ [H,3072]
        hgemm<EPI_F32, false><<<dim3(QKVN / BN, S / BM, 1), 256>>>(
            xn, wqkv_i, qkvf, nullptr, S, QKVN, H, QKVN, QKVN, 0, 0, 1, 0, nullptr, 0, nullptr);

        rope_kernel<<<S, 256>>>();

        // scores = Q @ K^T (causal block skip)
        hgemm<EPI_F32, true><<<dim3(S / BN, S / BM, NH), 256>>>(
            q, kT, scores, nullptr, S, S, HD, S, S,
            (size_t)S * HD, (size_t)HD * S, NH / NKV, (size_t)S * S, nullptr, 0, nullptr);

        softmax_kernel<<<dim3(S, NH), 256>>>();

        // O = P @ V -> attn [s][head*HD+d]
        hgemm<EPI_H, false><<<dim3(HD / BN, S / BM, NH), 256>>>(
            p, v, nullptr, attn, S, HD, S, HD, H,
            (size_t)S * S, (size_t)S * HD, NH / NKV, (size_t)HD, nullptr, 0, nullptr);

        // h += attn @ wo
        hgemm<EPI_ADDF32, false><<<dim3(H / BN, S / BM, 1), 256>>>(
            attn, wo_i, h_, nullptr, S, H, H, H, H, 0, 0, 1, 0, nullptr, 0, nullptr);

        // ---- token-partitioned MLP: each token runs ONLY its branch ----
        // gather + norm into compact order (text rows [0,cnt), audio rows [cnt,S))
        rmsnorm_gather<<<S, 256>>>(h_, ln_post_text + (size_t)i * H,
                                   ln_post_audio + (size_t)i * H, xc);

        // fc: text rows with wfc_text, audio rows with wfc_audio
        hgemm<EPI_SILUH, false><<<dim3(FF / BN, S / BM, 1), 256>>>(
            xc, wfct_i, nullptr, f1, S, FF, H, FF, FF, 0, 0, 1, 0, cnt, 1, nullptr);
        hgemm<EPI_SILUH, false><<<dim3(FF / BN, S / BM, 1), 256>>>(
            xc, wfca_i, nullptr, f1, S, FF, H, FF, FF, 0, 0, 1, 0, cnt, 2, nullptr);

        // proj + scatter-add back to residual (compact row -> original token)
        hgemm<EPI_SCATTER, false><<<dim3(H / BN, S / BM, 1), 256>>>(
            f1, wprt_i, h_, nullptr, S, H, FF, H, H, 0, 0, 1, 0, cnt, 1, idx);
        hgemm<EPI_SCATTER, false><<<dim3(H / BN, S / BM, 1), 256>>>(
            f1, wpra_i, h_, nullptr, S, H, FF, H, H, 0, 0, 1, 0, cnt, 2, idx);
    }

    rmsnorm_kernel<false><<<S, 256>>>(h_, lnf, lnf, nullptr, nullptr, out);
}